// round 17
// baseline (speedup 1.0000x reference)
#include <cuda_runtime.h>
#include <math_constants.h>

#define DIMV   64
#define KHALF  512          // folded frequencies k = 1..512
#define MAXP   32
#define MAXPTS 16384
#define KCHUNK 16           // k's per in-kernel chunk iteration (k3)
#define PTCH   32           // point-chunks (k3 grid.x)
#define KSTAGE 32           // A/B smem staging depth in k4
#define PLANE  16           // p slices

// ---------------- device scratch (static: no allocation allowed) ----------
// Replay-safety: g_max_sq updated only via atomicMax of a pure function of
// the inputs (idempotent). g_done is incremented per block and reset to 0 by
// the last block every call. g_sf2pi/g_g/g_kmax are overwritten every call by
// the k1 epilogue. g_c/g_s are zeroed every call in k1.
__device__ float g_max_sq;                    // max squared row norm
__device__ int   g_done;                      // k1 block-completion counter
__device__ float g_sf2pi;                     // 2*pi*X_RANGE/max_norm
__device__ float g_g[KHALF + 1];              // g[k] = w_k * kft(k) / P
__device__ int   g_kmax;                      // largest k with g[k] > 0
__device__ float g_dx[MAXP * MAXPTS];         // [p][i] proj (x . xi_p)/|xi_p|
__device__ float g_dy[MAXPTS * PLANE];        // [j][p] proj (y . xi_p)/|xi_p|
__device__ float g_c[MAXP * KHALF];           // adjoint cos sums
__device__ float g_s[MAXP * KHALF];           // adjoint sin sums

// g[k] = w_k * kft(k) / P  — pure function of (s2, P).
__device__ __forceinline__ float eval_g(int k, float s2, float invP) {
    float kf = (float)k;
    float lg = 32.f * logf(CUDART_PI_F)
             + 32.f * logf(2.f * CUDART_PI_F * s2)
             - lgammaf(32.f)
             + 63.f * logf(kf)
             - 2.f * CUDART_PI_F * CUDART_PI_F * s2 * kf * kf;
    float kft = expf(lg);
    float wk  = (k < KHALF) ? 2.f : 1.f;      // symmetry weight; k=512 unpaired
    return kft * wk * invP;
}

__device__ __forceinline__ float decode_scale(const int* scale_raw) {
    int iv = *scale_raw;                       // int32 or float32 bits
    return (iv > -10000000 && iv < 10000000) ? (float)iv : __int_as_float(iv);
}

// ---------------- kernel 1: projections + norm max + table epilogue -------
// 16 threads per row; thread owns slice p = tid&15 completely. xi staged
// transposed [q][p] float4 -> 16 lanes read consecutive p: conflict-free
// LDS.128. Row float4 is uniform within the 16-lane group (broadcast LDG).
// The LAST block to finish computes the g[k] table + kmax (k2 fully fused).
__global__ void __launch_bounds__(256) k1(const float* __restrict__ x,
                                          const float* __restrict__ y,
                                          const float* __restrict__ xis,
                                          const int* __restrict__ scl,
                                          int N, int M, int P) {
    __shared__ float4 sxiT[DIMV / 4][PLANE];   // [q][p] transposed
    __shared__ float  sinv[PLANE];
    for (int i = threadIdx.x; i < PLANE * (DIMV / 4); i += 256) {
        int p = i / (DIMV / 4), q = i % (DIMV / 4);
        float4 t = make_float4(0.f, 0.f, 0.f, 0.f);
        if (p < P) t = ((const float4*)xis)[p * (DIMV / 4) + q];
        sxiT[q][p] = t;
    }
    __syncthreads();
    if (threadIdx.x < PLANE) {
        int p = threadIdx.x;
        float ss = 0.f;
        #pragma unroll
        for (int q = 0; q < DIMV / 4; q++) {
            float4 t = sxiT[q][p];
            ss = fmaf(t.x, t.x, ss); ss = fmaf(t.y, t.y, ss);
            ss = fmaf(t.z, t.z, ss); ss = fmaf(t.w, t.w, ss);
        }
        sinv[p] = (p < P) ? 1.0f / sqrtf(ss) : 0.f;
    }
    __syncthreads();

    int tid = blockIdx.x * blockDim.x + threadIdx.x;
    if (tid < MAXP * KHALF) { g_c[tid] = 0.f; g_s[tid] = 0.f; }

    int r = tid >> 4;             // row
    int p = tid & 15;             // owned slice
    float v = 0.f;
    if (r < N + M) {
        const float4* row4 = (const float4*)((r < N) ? x + (size_t)r * DIMV
                                                     : y + (size_t)(r - N) * DIMV);
        float d0 = 0.f, d1 = 0.f;     // 2-chain dot
        float ssp = 0.f;              // partial row norm (this lane's q == p slice)
        #pragma unroll
        for (int q = 0; q < DIMV / 4; q++) {
            float4 t  = row4[q];                // uniform within 16-lane group
            float4 xa = sxiT[q][p];             // conflict-free across lanes
            d0 = fmaf(t.x, xa.x, d0); d1 = fmaf(t.y, xa.y, d1);
            d0 = fmaf(t.z, xa.z, d0); d1 = fmaf(t.w, xa.w, d1);
            if (q == p) {                       // 4-FMA norm share
                ssp = fmaf(t.x, t.x, ssp); ssp = fmaf(t.y, t.y, ssp);
                ssp = fmaf(t.z, t.z, ssp); ssp = fmaf(t.w, t.w, ssp);
            }
        }
        #pragma unroll
        for (int o = 1; o < 16; o <<= 1)        // sum partials within 16-group
            ssp += __shfl_xor_sync(0xffffffffu, ssp, o);
        v = ssp;                                // full row norm
        float d = (d0 + d1) * sinv[p];
        if (p < P) {
            if (r < N) g_dx[p * N + r] = d;
            else       g_dy[(r - N) * PLANE + p] = d;   // 64B contiguous per group
        }
    }
    // block max of row norms -> global atomicMax
    #pragma unroll
    for (int o = 16; o; o >>= 1) v = fmaxf(v, __shfl_down_sync(0xffffffffu, v, o));
    __shared__ float sm[8];
    if ((threadIdx.x & 31) == 0) sm[threadIdx.x >> 5] = v;
    __syncthreads();
    if (threadIdx.x < 8) {
        v = sm[threadIdx.x];
        #pragma unroll
        for (int o = 4; o; o >>= 1) v = fmaxf(v, __shfl_down_sync(0xffu, v, o));
        if (threadIdx.x == 0)
            atomicMax((int*)&g_max_sq, __float_as_int(v));  // non-negative floats: int-order ok
    }

    // ---- last-block epilogue: build g[k] table, kmax, sf (replaces k2) ----
    __shared__ int slast;
    __shared__ int skmax;
    __threadfence();                              // publish atomicMax + stores
    if (threadIdx.x == 0) {
        int seen = atomicAdd(&g_done, 1);
        slast = (seen == (int)gridDim.x - 1);
        skmax = 0;
    }
    __syncthreads();
    if (slast) {
        float msq = *(volatile float*)&g_max_sq;  // complete: all blocks arrived
        float sf  = 0.3f / sqrtf(msq);
        float s   = decode_scale(scl) * sf;
        float s2  = s * s;
        float invP = 1.0f / (float)P;
        int local = 0;
        for (int k = threadIdx.x + 1; k <= KHALF; k += 256) {
            float g = eval_g(k, s2, invP);
            g_g[k] = g;
            if (g > 0.f) local = k;               // k increasing across strides
        }
        if (local) atomicMax(&skmax, local);
        __syncthreads();
        if (threadIdx.x == 0) {
            g_kmax  = skmax;
            g_sf2pi = 2.f * CUDART_PI_F * sf;
            g_done  = 0;                          // reset for next graph replay
        }
    }
}

// ---------------- kernel 3: adjoint trig sums (projections precomputed) ---
// grid (PTCH, P). Table read from globals (computed once in k1 epilogue).
__global__ void __launch_bounds__(256) k3(const float* __restrict__ w, int N) {
    int kmax = g_kmax;
    float sf2pi = g_sf2pi;
    int p = blockIdx.y;
    int chunk = (N + PTCH - 1) / PTCH;
    int i0 = blockIdx.x * chunk;
    int i1 = min(N, i0 + chunk);
    int lane = threadIdx.x & 31, wid = threadIdx.x >> 5;
    const float* dx = g_dx + (size_t)p * N;
    __shared__ float red[8][2 * KCHUNK];

    for (int k0 = 1; k0 <= kmax; k0 += KCHUNK) {
        float ac[KCHUNK], as_[KCHUNK];
        #pragma unroll
        for (int j = 0; j < KCHUNK; j++) { ac[j] = 0.f; as_[j] = 0.f; }
        for (int i = i0 + threadIdx.x; i < i1; i += blockDim.x) {
            float th = sf2pi * dx[i];
            float wt = w[i];
            float st, ct; sincosf(th, &st, &ct);          // rotation step
            float sk, ck;
            if (k0 == 1) { ck = ct; sk = st; }            // common case: skip 2nd sincos
            else         sincosf((float)k0 * th, &sk, &ck);
            #pragma unroll
            for (int j = 0; j < KCHUNK; j++) {
                ac[j]  = fmaf(wt, ck, ac[j]);
                as_[j] = fmaf(wt, sk, as_[j]);
                float nc = fmaf(ck, ct, -sk * st);
                float ns = fmaf(sk, ct,  ck * st);
                ck = nc; sk = ns;
            }
        }
        #pragma unroll
        for (int j = 0; j < KCHUNK; j++) {
            float vc = ac[j], vs = as_[j];
            #pragma unroll
            for (int o = 16; o; o >>= 1) {
                vc += __shfl_down_sync(0xffffffffu, vc, o);
                vs += __shfl_down_sync(0xffffffffu, vs, o);
            }
            if (lane == 0) { red[wid][j] = vc; red[wid][KCHUNK + j] = vs; }
        }
        __syncthreads();
        for (int t = threadIdx.x; t < 2 * KCHUNK; t += blockDim.x) {
            float tot = 0.f;
            #pragma unroll
            for (int wdx = 0; wdx < 8; wdx++) tot += red[wdx][t];
            int k = k0 + (t & (KCHUNK - 1));
            if (k <= kmax) {
                float* dst = (t < KCHUNK) ? g_c : g_s;
                atomicAdd(&dst[p * KHALF + (k - 1)], tot);
            }
        }
        __syncthreads();   // red[] reused next chunk iteration
    }
}

// ---------------- kernel 4: forward NDFT (projections precomputed) --------
// grid = j-tiles (16 points x 16 p-lanes per block). Table from globals.
__global__ void __launch_bounds__(256) k4(float* __restrict__ out, int M, int P) {
    __shared__ float sAc[KSTAGE][MAXP];           // transposed: lane p -> bank p
    __shared__ float sAs[KSTAGE][MAXP];
    int kmax = g_kmax;
    int kst  = min(kmax, KSTAGE);
    for (int i = threadIdx.x; i < P * kst; i += blockDim.x) {
        int p = i / kst, k = (i % kst) + 1;
        float g = g_g[k];
        sAc[k - 1][p] = g * g_c[p * KHALF + k - 1];
        sAs[k - 1][p] = g * g_s[p * KHALF + k - 1];
    }
    __syncthreads();

    float sf2pi = g_sf2pi;
    int sub = threadIdx.x & 15;           // slice lane
    int pt  = threadIdx.x >> 4;           // point within tile
    int j   = blockIdx.x * 16 + pt;
    float acc = 0.f;
    if (j < M) {
        for (int p = sub; p < P; p += 16) {
            float th = sf2pi * g_dy[j * PLANE + p];   // 64B-contiguous across lanes
            float st, ct; sincosf(th, &st, &ct);
            float ck = ct, sk = st;
            for (int k = 0; k < kst; k++) {
                acc = fmaf(sAc[k][p], ck, acc);
                acc = fmaf(sAs[k][p], sk, acc);
                float nc = fmaf(ck, ct, -sk * st);
                float ns = fmaf(sk, ct,  ck * st);
                ck = nc; sk = ns;
            }
            for (int k = kst + 1; k <= kmax; k++) {   // rare tail (kmax > KSTAGE)
                float g = g_g[k];
                acc = fmaf(g * g_c[p * KHALF + k - 1], ck, acc);
                acc = fmaf(g * g_s[p * KHALF + k - 1], sk, acc);
                float nc = fmaf(ck, ct, -sk * st);
                float ns = fmaf(sk, ct,  ck * st);
                ck = nc; sk = ns;
            }
        }
    }
    #pragma unroll
    for (int o = 8; o; o >>= 1)
        acc += __shfl_down_sync(0xffffffffu, acc, o, 16);  // reduce 16-lane group
    if (sub == 0 && j < M) out[j] = acc;   // w_k and 1/P folded into g[k]
}

// ---------------- launch ---------------------------------------------------
extern "C" void kernel_launch(void* const* d_in, const int* in_sizes, int n_in,
                              void* d_out, int out_size) {
    const float* x   = (const float*)d_in[0];
    const float* y   = (const float*)d_in[1];
    const float* w   = (const float*)d_in[2];
    const float* xis = (const float*)d_in[3];
    const int*   scl = (const int*)d_in[4];
    int N = in_sizes[0] / DIMV;
    int M = in_sizes[1] / DIMV;
    int P = in_sizes[3] / DIMV;

    int n1 = max((N + M) * 16, MAXP * KHALF);
    k1<<<(n1 + 255) / 256, 256>>>(x, y, xis, scl, N, M, P);
    dim3 gc(PTCH, P);
    k3<<<gc, 256>>>(w, N);
    k4<<<(M + 15) / 16, 256>>>((float*)d_out, M, P);
}